// round 3
// baseline (speedup 1.0000x reference)
#include <cuda_runtime.h>

#define NN 2000
#define NE 40000
#define NB 4
#define NT 34
#define TP 32
#define BT 128          // NB * TP
#define NC 32           // channels (C_IN == DC == 32)

// ---------------- device scratch (static, no runtime alloc) ----------------
__device__ float d_hw[BT * NN * NC];     // (bt, n, ch)  32 MB — gated conv -> gcn_w result
__device__ float d_deg[NN];
__device__ float d_dis[NN];
__device__ float d_selfnorm[NN];
__device__ int   d_cnt[NN];
__device__ int   d_start[NN + 1];
__device__ int   d_cursor[NN];
__device__ int   d_src[NE];
__device__ float d_cnorm[NE];
__device__ int   d_is64;                 // edge_index stored as int64?

// ---------------- edge index access (dtype-robust) ----------------
__device__ __forceinline__ int edge_at(const int* __restrict__ ei, int idx) {
    return d_is64 ? ei[2 * idx] : ei[idx];
}

__global__ void k_detect(const int* __restrict__ ei) {
    // int64 little-endian node ids < 2000 => every odd 32-bit word is 0.
    // For int32 data those words are random node ids (P[all 128 zero] ~ 0).
    int lane = threadIdx.x;
    int nz = 0;
    for (int i = lane; i < 128; i += 32)
        if (ei[2 * i + 1] != 0) nz = 1;
    unsigned any = __ballot_sync(0xffffffffu, nz);
    if (lane == 0) d_is64 = (any == 0u) ? 1 : 0;
}

// ---------------- small setup kernels ----------------
__global__ void k_init() {
    int n = blockIdx.x * blockDim.x + threadIdx.x;
    if (n < NN) { d_deg[n] = 1.0f; d_cnt[n] = 0; }   // self-loop weight = 1
}

__global__ void k_count(const int* __restrict__ ei,
                        const float* __restrict__ ew) {
    int e = blockIdx.x * blockDim.x + threadIdx.x;
    if (e < NE) {
        int col = edge_at(ei, NE + e);
        atomicAdd(&d_deg[col], ew[e]);
        atomicAdd(&d_cnt[col], 1);
    }
}

__global__ void k_dis() {
    int n = blockIdx.x * blockDim.x + threadIdx.x;
    if (n < NN) {
        float r = rsqrtf(d_deg[n]);   // deg >= 1 always (self loop)
        d_dis[n] = r;
        d_selfnorm[n] = r * r;
    }
}

// exclusive prefix sum over d_cnt -> d_start / d_cursor  (single block, 1024 thr, 2 elems/thread)
__global__ void k_scan() {
    __shared__ int sh[1024];
    int t = threadIdx.x;
    int i0 = 2 * t, i1 = 2 * t + 1;
    int a = (i0 < NN) ? d_cnt[i0] : 0;
    int b = (i1 < NN) ? d_cnt[i1] : 0;
    int s = a + b;
    sh[t] = s;
    __syncthreads();
    for (int off = 1; off < 1024; off <<= 1) {
        int v = (t >= off) ? sh[t - off] : 0;
        __syncthreads();
        sh[t] += v;
        __syncthreads();
    }
    int excl = sh[t] - s;
    if (i0 < NN) { d_start[i0] = excl;     d_cursor[i0] = excl; }
    if (i1 < NN) { d_start[i1] = excl + a; d_cursor[i1] = excl + a; }
    if (t == 1023) d_start[NN] = sh[1023];
}

__global__ void k_fill(const int* __restrict__ ei,
                       const float* __restrict__ ew) {
    int e = blockIdx.x * blockDim.x + threadIdx.x;
    if (e < NE) {
        int row = edge_at(ei, e);
        int col = edge_at(ei, NE + e);
        float nw = d_dis[row] * ew[e] * d_dis[col];
        int pos = atomicAdd(&d_cursor[col], 1);
        d_src[pos]   = row;
        d_cnorm[pos] = nw;
    }
}

// ---------------- gate conv + tanh*sigmoid + gcn_w GEMM ----------------
// one warp per (bt, n); lane = channel. x: (4, 34, 2000, 32) fp32.
__global__ void __launch_bounds__(256) k_gate(
    const float* __restrict__ x,
    const float* __restrict__ g1w, const float* __restrict__ g1b,
    const float* __restrict__ g2w, const float* __restrict__ g2b,
    const float* __restrict__ gw)
{
    __shared__ float4 wpack[32][32];   // [c][dc] = (w1a, w1b, w2a, w2b)
    __shared__ float  gsh[32][32];     // [dc][ch]
    int tid = threadIdx.x;
    for (int i = tid; i < 1024; i += 256) {
        int dc = i & 31, c = i >> 5;
        wpack[c][dc] = make_float4(g1w[dc * 64 + c * 2], g1w[dc * 64 + c * 2 + 1],
                                   g2w[dc * 64 + c * 2], g2w[dc * 64 + c * 2 + 1]);
        gsh[i >> 5][i & 31] = gw[i];   // gw[dc*32 + ch]
    }
    __syncthreads();

    int lane = tid & 31, wid = tid >> 5;
    float b1 = g1b[lane], b2 = g2b[lane];
    int nwarps = gridDim.x * 8;

    for (int task = blockIdx.x * 8 + wid; task < BT * NN; task += nwarps) {
        int bt = task / NN;
        int n  = task - bt * NN;
        int b  = bt >> 5, t = bt & 31;
        const float* xp = x + (((size_t)b * NT + t) * NN + n) * NC;
        float x0 = xp[lane];
        float x1 = xp[2 * NN * NC + lane];

        float acc1 = b1, acc2 = b2;
        #pragma unroll
        for (int c = 0; c < 32; ++c) {
            float v0 = __shfl_sync(0xffffffffu, x0, c);
            float v1 = __shfl_sync(0xffffffffu, x1, c);
            float4 w = wpack[c][lane];
            acc1 = fmaf(v0, w.x, acc1);
            acc1 = fmaf(v1, w.y, acc1);
            acc2 = fmaf(v0, w.z, acc2);
            acc2 = fmaf(v1, w.w, acc2);
        }
        float h = tanhf(acc1) * (1.0f / (1.0f + expf(-acc2)));

        float acc = 0.0f;
        #pragma unroll
        for (int dc = 0; dc < 32; ++dc) {
            float hv = __shfl_sync(0xffffffffu, h, dc);
            acc = fmaf(hv, gsh[dc][lane], acc);
        }
        d_hw[(size_t)task * NC + lane] = acc;
    }
}

// ---------------- CSR gather (atomic-free scatter) ----------------
// one warp per (n, bt); lane = channel.  out: (B, Tp, N, C) = (bt, n, ch)
__global__ void __launch_bounds__(256) k_gather(
    const float* __restrict__ gb, float* __restrict__ out)
{
    int tid = threadIdx.x;
    int lane = tid & 31, wid = tid >> 5;
    float bias = gb[lane];
    int nwarps = gridDim.x * 8;

    for (int task = blockIdx.x * 8 + wid; task < BT * NN; task += nwarps) {
        int n  = task >> 7;       // same n across consecutive tasks -> CSR row reuse
        int bt = task & 127;
        const float* hwbt = d_hw + (size_t)bt * NN * NC;
        float acc = d_selfnorm[n] * hwbt[n * NC + lane];
        int s = d_start[n], e = d_start[n + 1];
        for (int k = s; k < e; ++k) {
            int   src = __ldg(&d_src[k]);
            float nw  = __ldg(&d_cnorm[k]);
            acc = fmaf(nw, hwbt[src * NC + lane], acc);
        }
        out[((size_t)bt * NN + n) * NC + lane] = acc + bias;
    }
}

// ---------------- launch ----------------
extern "C" void kernel_launch(void* const* d_in, const int* in_sizes, int n_in,
                              void* d_out, int out_size)
{
    const float* x   = (const float*)d_in[0];
    const int*   ei  = (const int*)d_in[1];
    const float* ew  = (const float*)d_in[2];
    const float* g1w = (const float*)d_in[3];
    const float* g1b = (const float*)d_in[4];
    const float* g2w = (const float*)d_in[5];
    const float* g2b = (const float*)d_in[6];
    const float* gw  = (const float*)d_in[7];
    const float* gb  = (const float*)d_in[8];
    float* out = (float*)d_out;

    k_detect<<<1, 32>>>(ei);
    k_init<<<(NN + 255) / 256, 256>>>();
    k_count<<<(NE + 255) / 256, 256>>>(ei, ew);
    k_dis<<<(NN + 255) / 256, 256>>>();
    k_scan<<<1, 1024>>>();
    k_fill<<<(NE + 255) / 256, 256>>>(ei, ew);
    k_gate<<<1184, 256>>>(x, g1w, g1b, g2w, g2b, gw);
    k_gather<<<1184, 256>>>(gb, out);
}